// round 1
// baseline (speedup 1.0000x reference)
#include <cuda_runtime.h>
#include <cuda_bf16.h>
#include <math.h>

#define MAX_N 8192
#define TPB 256           // threads per block (pairwise kernel)
#define CPT 4             // columns held in registers per thread
#define ROWS 128          // rows per block tile (staged in shared)

// Scratch (no allocations allowed)
__device__ float              g_u[MAX_N];   // u_i = pred_i - logit(psi_i)
__device__ double             g_bce;
__device__ double             g_sq;
__device__ unsigned long long g_cnt;

__global__ void init_kernel() {
    g_bce = 0.0;
    g_sq  = 0.0;
    g_cnt = 0ull;
}

// Compute BCE partial sums and u[] in one pass.
__global__ void prep_kernel(const float* __restrict__ pred,
                            const float* __restrict__ psi, int n) {
    float part = 0.f;
    for (int i = blockIdx.x * blockDim.x + threadIdx.x; i < n;
         i += gridDim.x * blockDim.x) {
        float x = pred[i];
        float t = psi[i];
        // stable BCE-with-logits term
        part += fmaxf(x, 0.f) - x * t + log1pf(expf(-fabsf(x)));
        // logit with clamp [eps, 1-eps]
        float p = fminf(fmaxf(t, 1e-7f), 1.0f - 1e-7f);
        float L = logf(p) - log1pf(-p);
        g_u[i] = x - L;
    }
    #pragma unroll
    for (int o = 16; o; o >>= 1)
        part += __shfl_xor_sync(0xffffffffu, part, o);
    if ((threadIdx.x & 31) == 0)
        atomicAdd(&g_bce, (double)part);
}

// All-pairs masked sum of (u_i - u_j)^2 and valid count.
// grid.x: column tiles of TPB*CPT, grid.y: row tiles of ROWS.
__global__ void pair_kernel(const float* __restrict__ psi, int n) {
    __shared__ float s_u[ROWS];
    __shared__ float s_p[ROWS];

    const int cbase = blockIdx.x * (TPB * CPT) + threadIdx.x * CPT;
    float uc[CPT], pc[CPT];
    bool  ok[CPT];
    #pragma unroll
    for (int k = 0; k < CPT; k++) {
        int c = cbase + k;
        ok[k] = (c < n);
        uc[k] = ok[k] ? g_u[c]  : 0.f;
        pc[k] = ok[k] ? psi[c]  : 1e9f;  // never "valid" vs masked pc? masked via ok[]
    }

    const int r0 = blockIdx.y * ROWS;
    if (threadIdx.x < ROWS) {
        int r = r0 + threadIdx.x;
        s_u[threadIdx.x] = (r < n) ? g_u[r] : 0.f;
        s_p[threadIdx.x] = (r < n) ? psi[r] : 0.f;
    }
    __syncthreads();

    const int rend = min(ROWS, n - r0);
    float acc = 0.f;
    int   cnt = 0;
    for (int i = 0; i < rend; i++) {
        float ui = s_u[i];   // broadcast LDS
        float pi = s_p[i];
        #pragma unroll
        for (int k = 0; k < CPT; k++) {
            float dp = pi - pc[k];          // identical op order to reference
            float du = ui - uc[k];
            bool  v  = ok[k] && (fabsf(dp) >= 0.05f);
            if (v) {
                acc = fmaf(du, du, acc);
                cnt++;
            }
        }
    }

    #pragma unroll
    for (int o = 16; o; o >>= 1) {
        acc += __shfl_xor_sync(0xffffffffu, acc, o);
        cnt += __shfl_xor_sync(0xffffffffu, cnt, o);
    }
    if ((threadIdx.x & 31) == 0) {
        atomicAdd(&g_sq, (double)acc);
        atomicAdd(&g_cnt, (unsigned long long)cnt);
    }
}

__global__ void final_kernel(const int* __restrict__ flag, float* __restrict__ out, int n) {
    double loss = g_bce / (double)n;
    if (!(*flag) && g_cnt > 0ull)
        loss += 10.0 * (g_sq / (double)g_cnt);
    out[0] = (float)loss;
}

extern "C" void kernel_launch(void* const* d_in, const int* in_sizes, int n_in,
                              void* d_out, int out_size) {
    const float* pred = (const float*)d_in[0];
    const float* psi  = (const float*)d_in[1];
    const int*   flag = (const int*)d_in[2];
    float*       out  = (float*)d_out;
    const int n = in_sizes[0];

    init_kernel<<<1, 1>>>();
    prep_kernel<<<64, 256>>>(pred, psi, n);

    dim3 grid((n + TPB * CPT - 1) / (TPB * CPT),
              (n + ROWS - 1) / ROWS);
    pair_kernel<<<grid, TPB>>>(psi, n);

    final_kernel<<<1, 1>>>(flag, out, n);
}